// round 15
// baseline (speedup 1.0000x reference)
#include <cuda_runtime.h>
#include <cuda_fp16.h>
#include <math.h>
#include <stdint.h>

// Problem constants
#define NN      50000
#define DH      128
#define S_NEI   25
#define MT      64                         // rows per tile
#define NTILES  ((NN + MT - 1) / MT)       // 782
#define NB      444                        // persistent grid: 148 SMs x 3 CTAs

// ---------------- scratch (device globals; no allocation allowed) -----------
__device__ __align__(16) __half g_h1 [(size_t)NN * DH];
__device__ __align__(16) __half g_f16[(size_t)NN * DH];
__device__ __align__(16) __half g_x1 [(size_t)NN * DH];
__device__ __align__(16) __half g_xn [(size_t)NN * DH];
__device__ __align__(16) __half g_h2 [(size_t)NN * DH];
__device__ float g_sum[DH];
__device__ float g_sq[DH];
// fragment-packed fp16 weights
__device__ __align__(16) uint2 g_w1p [ 8 * 16 * 32];
__device__ __align__(16) uint2 g_wf1p[16 * 16 * 32];
__device__ __align__(16) uint2 g_w2p [ 8 * 16 * 32];
__device__ __align__(16) uint2 g_wf2p[16 * 16 * 32];
// device-wide barrier state (zero-initialized; reset by cleanup each launch)
__device__ unsigned g_cnt[5];
__device__ unsigned g_flag[4];

// ---------------- device-wide barrier -----------------------------------------
__device__ __forceinline__ void gbar(int i) {
    __syncthreads();
    if (threadIdx.x == 0) {
        __threadfence();
        if (atomicAdd(&g_cnt[i], 1u) + 1u == (unsigned)NB) {
            atomicExch(&g_flag[i], 1u);
        } else {
            while (atomicAdd(&g_flag[i], 0u) == 0u) __nanosleep(64);
        }
        __threadfence();
    }
    __syncthreads();
}

// ---------------- fp16 MMA ----------------------------------------------------
__device__ __forceinline__ void mma_f16(float* c, const uint32_t* a,
                                        const uint32_t* b) {
    asm volatile(
        "mma.sync.aligned.m16n8k16.row.col.f32.f16.f16.f32 "
        "{%0,%1,%2,%3}, {%4,%5,%6,%7}, {%8,%9}, {%0,%1,%2,%3};\n"
        : "+f"(c[0]), "+f"(c[1]), "+f"(c[2]), "+f"(c[3])
        : "r"(a[0]), "r"(a[1]), "r"(a[2]), "r"(a[3]), "r"(b[0]), "r"(b[1]));
}

__device__ __forceinline__ void store2(float* p, float x0, float x1) {
    *(float2*)p = make_float2(x0, x1);
}
__device__ __forceinline__ void store2(__half* p, float x0, float x1) {
    *(__half2*)p = __floats2half2_rn(x0, x1);
}

// ---------------- weight pack (phase 0 body) -----------------------------------
__device__ void pack_one(int b, const float* __restrict__ w1,
                         const float* __restrict__ f1,
                         const float* __restrict__ w2,
                         const float* __restrict__ f2) {
    const float* src; uint2* dst; int kb;
    if      (b < 8)  { src = w1; dst = g_w1p;  kb = b;      }
    else if (b < 24) { src = f1; dst = g_wf1p; kb = b - 8;  }
    else if (b < 32) { src = w2; dst = g_w2p;  kb = b - 24; }
    else             { src = f2; dst = g_wf2p; kb = b - 32; }
#pragma unroll
    for (int s = 0; s < 2; ++s) {
        int e    = threadIdx.x + s * 256;
        int cg   = e >> 5, lane = e & 31;
        int col  = cg * 8 + (lane >> 2);
        int tig  = lane & 3;
        int k0   = kb * 16 + 2 * tig;
        __half2 p0 = __floats2half2_rn(src[(k0    ) * DH + col],
                                       src[(k0 + 1) * DH + col]);
        __half2 p1 = __floats2half2_rn(src[(k0 + 8) * DH + col],
                                       src[(k0 + 9) * DH + col]);
        uint2 o;
        o.x = *(uint32_t*)&p0;
        o.y = *(uint32_t*)&p1;
        dst[(kb * 16 + cg) * 32 + lane] = o;
    }
}

// ---------------- barrier-free fp16 GEMM core ----------------------------------
template<int KDIM>
__device__ __forceinline__ void gemm_f16(const __half* __restrict__ As,
                                         const uint2* __restrict__ Wp,
                                         int tid, float acc[2][4][4])
{
    constexpr int KPADH = KDIM + 8;
    constexpr int NKB   = KDIM / 16;
    const int gid = (tid & 31) >> 2, tig = tid & 3;
    const int wm  = (tid >> 5) >> 2, wn  = (tid >> 5) & 3;
    const uint2* wbase = Wp + (wn * 4) * 32 + (tid & 31);

    __syncthreads();   // publishes As

#pragma unroll 4
    for (int kb = 0; kb < NKB; ++kb) {
        uint2 bv[4];
#pragma unroll
        for (int ni = 0; ni < 4; ++ni)
            bv[ni] = __ldg(wbase + kb * 512 + ni * 32);

        uint32_t a[2][4];
#pragma unroll
        for (int mi = 0; mi < 2; ++mi) {
            const __half* ap = As + (wm * 32 + mi * 16 + gid) * KPADH
                                  + kb * 16 + 2 * tig;
            a[mi][0] = *(const uint32_t*)ap;
            a[mi][1] = *(const uint32_t*)(ap + 8 * KPADH);
            a[mi][2] = *(const uint32_t*)(ap + 8);
            a[mi][3] = *(const uint32_t*)(ap + 8 * KPADH + 8);
        }
#pragma unroll
        for (int mi = 0; mi < 2; ++mi)
#pragma unroll
            for (int ni = 0; ni < 4; ++ni)
                mma_f16(acc[mi][ni], a[mi], (const uint32_t*)&bv[ni]);
    }
}

// ---------------- layer phase (persistent tile loop) ---------------------------
template<int KDIM, bool RELU, bool GATHER, bool STATS,
         bool FEAT16, bool WRITEF16, typename OUTT>
__device__ void layer_phase(const float*  __restrict__ Xf,
                            const __half* __restrict__ Xh,
                            const __half* __restrict__ Htab,
                            const int*    __restrict__ nidx,
                            const uint2*  __restrict__ Wp,
                            const float*  __restrict__ bias,
                            OUTT*   __restrict__ out,
                            __half* __restrict__ f16out,
                            float*  __restrict__ gsum,
                            float*  __restrict__ gsq)
{
    extern __shared__ __half sm[];
    constexpr int KPADH = KDIM + 8;
    __half* As  = sm;
    float*  Sst = (float*)(sm + MT * KPADH);

    const int tid  = threadIdx.x;
    const int lane = tid & 31, wrp = tid >> 5;
    const int gid  = lane >> 2, tig = lane & 3;
    const int wm   = wrp >> 2,  wn  = wrp & 3;

    float2 bb[4];
#pragma unroll
    for (int ni = 0; ni < 4; ++ni)
        bb[ni] = *(const float2*)(bias + wn * 32 + ni * 8 + 2 * tig);

    for (int tile = blockIdx.x; tile < NTILES; tile += NB) {
        const int m0 = tile * MT;

        __syncthreads();   // guard As/Sst reuse across tile iterations
        if (STATS) Sst[tid] = 0.f;

        // ---- stage A tile ----
#pragma unroll
        for (int q = 0; q < MT / 8; ++q) {
            int lr = wrp * (MT / 8) + q;
            int r  = m0 + lr; if (r >= NN) r = NN - 1;

            if (FEAT16) {
                uint2 v = *(const uint2*)(Xh + (size_t)r * DH + lane * 4);
                *(uint2*)(As + lr * KPADH + lane * 4) = v;
            } else {
                float4 f = *(const float4*)(Xf + (size_t)r * DH + lane * 4);
                __half2 h0 = __floats2half2_rn(f.x, f.y);
                __half2 h1 = __floats2half2_rn(f.z, f.w);
                uint2 v;
                v.x = *(uint32_t*)&h0; v.y = *(uint32_t*)&h1;
                *(uint2*)(As + lr * KPADH + lane * 4) = v;
                if (WRITEF16)
                    *(uint2*)(f16out + (size_t)r * DH + lane * 4) = v;
            }

            if (GATHER) {
                const int c  = lane & 15, hw = lane >> 4;
                const int* nb = nidx + r * S_NEI + hw * 12;
                __half2 mx0 = __float2half2_rn(0.f);  // post-relu >= 0
                __half2 mx1 = mx0, mx2 = mx0, mx3 = mx0;
#pragma unroll
                for (int t = 0; t < 13; ++t) {
                    int id = __ldg(nb + t);
                    uint4 v = *(const uint4*)(Htab + (size_t)id * DH + c * 8);
                    mx0 = __hmax2(mx0, *(__half2*)&v.x);
                    mx1 = __hmax2(mx1, *(__half2*)&v.y);
                    mx2 = __hmax2(mx2, *(__half2*)&v.z);
                    mx3 = __hmax2(mx3, *(__half2*)&v.w);
                }
                uint4 o;
                uint32_t* mo = (uint32_t*)&o;
                __half2 mx[4] = {mx0, mx1, mx2, mx3};
#pragma unroll
                for (int i = 0; i < 4; ++i) {
                    uint32_t mm = *(uint32_t*)&mx[i];
                    uint32_t ot = __shfl_xor_sync(0xffffffffu, mm, 16);
                    __half2 rr  = __hmax2(*(__half2*)&mm, *(__half2*)&ot);
                    mo[i] = *(uint32_t*)&rr;
                }
                if (hw == 0)
                    *(uint4*)(As + lr * KPADH + DH + c * 8) = o;
            }
        }

        float acc[2][4][4];
#pragma unroll
        for (int mi = 0; mi < 2; ++mi)
#pragma unroll
            for (int ni = 0; ni < 4; ++ni)
#pragma unroll
                for (int c = 0; c < 4; ++c) acc[mi][ni][c] = 0.f;

        gemm_f16<KDIM>(As, Wp, tid, acc);

        // ---- epilogue ----
        float ps[8], pq[8];
        if (STATS) {
#pragma unroll
            for (int j = 0; j < 8; ++j) { ps[j] = 0.f; pq[j] = 0.f; }
        }
#pragma unroll
        for (int mi = 0; mi < 2; ++mi) {
#pragma unroll
            for (int h = 0; h < 2; ++h) {
                int r = m0 + wm * 32 + mi * 16 + h * 8 + gid;
                if (r < NN) {
#pragma unroll
                    for (int ni = 0; ni < 4; ++ni) {
                        float x0 = acc[mi][ni][h * 2 + 0] + bb[ni].x;
                        float x1 = acc[mi][ni][h * 2 + 1] + bb[ni].y;
                        if (RELU) { x0 = fmaxf(x0, 0.f); x1 = fmaxf(x1, 0.f); }
                        if (STATS) {
                            ps[ni * 2]     += x0; pq[ni * 2]     += x0 * x0;
                            ps[ni * 2 + 1] += x1; pq[ni * 2 + 1] += x1 * x1;
                        }
                        store2(out + (size_t)r * DH + wn * 32 + ni * 8 + 2 * tig,
                               x0, x1);
                    }
                }
            }
        }

        if (STATS) {
#pragma unroll
            for (int j = 0; j < 8; ++j) {
#pragma unroll
                for (int o = 16; o >= 4; o >>= 1) {
                    ps[j] += __shfl_xor_sync(0xffffffffu, ps[j], o);
                    pq[j] += __shfl_xor_sync(0xffffffffu, pq[j], o);
                }
            }
            if (gid == 0) {
#pragma unroll
                for (int ni = 0; ni < 4; ++ni) {
                    int c = wn * 32 + ni * 8 + 2 * tig;
                    atomicAdd(Sst + c,           ps[ni * 2]);
                    atomicAdd(Sst + c + 1,       ps[ni * 2 + 1]);
                    atomicAdd(Sst + 128 + c,     pq[ni * 2]);
                    atomicAdd(Sst + 128 + c + 1, pq[ni * 2 + 1]);
                }
            }
            __syncthreads();
            if (tid < DH) {
                atomicAdd(gsum + tid, Sst[tid]);
                atomicAdd(gsq + tid,  Sst[128 + tid]);
            }
        }
    }
}

// ---------------- BN + rownorm + GEMM phase ------------------------------------
__device__ void bn_phase(const __half* __restrict__ X1,
                         const float* __restrict__ gsum,
                         const float* __restrict__ gsq,
                         const float* __restrict__ gamma,
                         const float* __restrict__ beta,
                         const uint2* __restrict__ Wp,
                         const float* __restrict__ bias,
                         __half* __restrict__ xn,
                         __half* __restrict__ h2)
{
    extern __shared__ __half sm[];
    constexpr int KPADH = DH + 8;
    __half* As = sm;

    const int tid  = threadIdx.x;
    const int lane = tid & 31, wrp = tid >> 5;
    const int gid  = lane >> 2, tig = tid & 3;
    const int wm   = wrp >> 2,  wn  = wrp & 3;

    float sc[4], sh[4];
    {
        const float invN = 1.f / (float)NN;
#pragma unroll
        for (int i = 0; i < 4; ++i) {
            int c = lane * 4 + i;
            float mean = __ldg(gsum + c) * invN;
            float var  = __ldg(gsq + c) * invN - mean * mean;
            float s    = rsqrtf(var + 1e-5f) * __ldg(gamma + c);
            sc[i] = s;
            sh[i] = __ldg(beta + c) - mean * s;
        }
    }

    float2 bb[4];
#pragma unroll
    for (int ni = 0; ni < 4; ++ni)
        bb[ni] = *(const float2*)(bias + wn * 32 + ni * 8 + 2 * tig);

    for (int tile = blockIdx.x; tile < NTILES; tile += NB) {
        const int m0 = tile * MT;

        __syncthreads();   // guard As reuse

        uint2 raw[MT / 8];
#pragma unroll
        for (int q = 0; q < MT / 8; ++q) {
            int r = m0 + wrp * (MT / 8) + q; if (r >= NN) r = NN - 1;
            raw[q] = *(const uint2*)(X1 + (size_t)r * DH + lane * 4);
        }

#pragma unroll
        for (int q = 0; q < MT / 8; ++q) {
            int lr = wrp * (MT / 8) + q;
            int r  = m0 + lr; if (r >= NN) r = NN - 1;
            float2 f0 = __half22float2(*(__half2*)&raw[q].x);
            float2 f1 = __half22float2(*(__half2*)&raw[q].y);
            float v0 = fmaf(f0.x, sc[0], sh[0]);
            float v1 = fmaf(f0.y, sc[1], sh[1]);
            float v2 = fmaf(f1.x, sc[2], sh[2]);
            float v3 = fmaf(f1.y, sc[3], sh[3]);
            float ss = v0 * v0 + v1 * v1 + v2 * v2 + v3 * v3;
#pragma unroll
            for (int o = 16; o; o >>= 1)
                ss += __shfl_xor_sync(0xffffffffu, ss, o);
            float inv = 1.f / (sqrtf(ss) + 1e-6f);
            v0 *= inv; v1 *= inv; v2 *= inv; v3 *= inv;
            __half2 h0 = __floats2half2_rn(v0, v1);
            __half2 h1 = __floats2half2_rn(v2, v3);
            uint2 v;
            v.x = *(uint32_t*)&h0; v.y = *(uint32_t*)&h1;
            *(uint2*)(As + lr * KPADH + lane * 4) = v;
            *(uint2*)(xn + (size_t)r * DH + lane * 4) = v;
        }

        float acc[2][4][4];
#pragma unroll
        for (int mi = 0; mi < 2; ++mi)
#pragma unroll
            for (int ni = 0; ni < 4; ++ni)
#pragma unroll
                for (int c = 0; c < 4; ++c) acc[mi][ni][c] = 0.f;

        gemm_f16<DH>(As, Wp, tid, acc);

#pragma unroll
        for (int mi = 0; mi < 2; ++mi) {
#pragma unroll
            for (int h = 0; h < 2; ++h) {
                int r = m0 + wm * 32 + mi * 16 + h * 8 + gid;
                if (r < NN) {
#pragma unroll
                    for (int ni = 0; ni < 4; ++ni) {
                        float x0 = fmaxf(acc[mi][ni][h * 2 + 0] + bb[ni].x, 0.f);
                        float x1 = fmaxf(acc[mi][ni][h * 2 + 1] + bb[ni].y, 0.f);
                        store2(h2 + (size_t)r * DH + wn * 32 + ni * 8 + 2 * tig,
                               x0, x1);
                    }
                }
            }
        }
    }
}

// ---------------- megakernel ---------------------------------------------------
__global__ void __launch_bounds__(256, 3)
mega_kernel(const float* __restrict__ features,
            const int*   __restrict__ idx1,
            const int*   __restrict__ idx2,
            const float* __restrict__ agg1_W, const float* __restrict__ agg1_b,
            const float* __restrict__ fc1_W,  const float* __restrict__ fc1_b,
            const float* __restrict__ agg2_W, const float* __restrict__ agg2_b,
            const float* __restrict__ fc2_W,  const float* __restrict__ fc2_b,
            const float* __restrict__ gamma,  const float* __restrict__ beta,
            float* __restrict__ out)
{
    // ---- phase 0: pack weights + zero BN stats ----
    if (blockIdx.x < 48)
        pack_one(blockIdx.x, agg1_W, fc1_W, agg2_W, fc2_W);
    if (blockIdx.x == NB - 1 && threadIdx.x < DH) {
        g_sum[threadIdx.x] = 0.f;
        g_sq[threadIdx.x]  = 0.f;
    }
    gbar(0);

    // ---- phase 1: h1 = relu(F @ W1 + b) -> fp16; emits fp16 features ----
    layer_phase<128, true, false, false, false, true, __half>(
        features, nullptr, nullptr, nullptr, g_w1p, agg1_b,
        g_h1, g_f16, nullptr, nullptr);
    gbar(1);

    // ---- phase 2: x1 = relu([F16 | max h1[idx1]] @ Wf1 + b) -> fp16; stats ----
    layer_phase<256, true, true, true, true, false, __half>(
        nullptr, g_f16, g_h1, idx1, g_wf1p, fc1_b,
        g_x1, nullptr, g_sum, g_sq);
    gbar(2);

    // ---- phase 3: xn = rownorm(BN(x1)); h2 = relu(xn @ W2 + b) ----
    bn_phase(g_x1, g_sum, g_sq, gamma, beta, g_w2p, agg2_b, g_xn, g_h2);
    gbar(3);

    // ---- phase 4: out = [xn | max h2[idx2]] @ Wf2 + b (fp32) ----
    layer_phase<256, false, true, false, true, false, float>(
        nullptr, g_xn, g_h2, idx2, g_wf2p, fc2_b,
        out, nullptr, nullptr, nullptr);

    // ---- cleanup: last CTA resets barrier state for the next graph replay ----
    __syncthreads();
    if (threadIdx.x == 0) {
        __threadfence();
        if (atomicAdd(&g_cnt[4], 1u) + 1u == (unsigned)NB) {
#pragma unroll
            for (int i = 0; i < 4; ++i) { g_cnt[i] = 0u; g_flag[i] = 0u; }
            g_cnt[4] = 0u;
            __threadfence();
        }
    }
}

// ---------------- host launch --------------------------------------------------
extern "C" void kernel_launch(void* const* d_in, const int* in_sizes, int n_in,
                              void* d_out, int out_size)
{
    const float* features = (const float*)d_in[0];
    const int*   idx1     = (const int*)  d_in[1];
    const int*   idx2     = (const int*)  d_in[2];
    const float* agg1_W   = (const float*)d_in[3];
    const float* agg1_b   = (const float*)d_in[4];
    const float* fc1_W    = (const float*)d_in[5];
    const float* fc1_b    = (const float*)d_in[6];
    const float* agg2_W   = (const float*)d_in[7];
    const float* agg2_b   = (const float*)d_in[8];
    const float* fc2_W    = (const float*)d_in[9];
    const float* fc2_b    = (const float*)d_in[10];
    const float* gamma    = (const float*)d_in[11];
    const float* beta     = (const float*)d_in[12];
    float* out = (float*)d_out;

    // max over phases: K=256 As (33792 B) + 256-float stats block = 34816 B
    const int smem = MT * (256 + 8) * 2 + 256 * (int)sizeof(float);

    cudaFuncSetAttribute((const void*)mega_kernel,
                         cudaFuncAttributeMaxDynamicSharedMemorySize, smem);

    mega_kernel<<<NB, 256, smem>>>(
        features, idx1, idx2,
        agg1_W, agg1_b, fc1_W, fc1_b,
        agg2_W, agg2_b, fc2_W, fc2_b,
        gamma, beta, out);
}